// round 16
// baseline (speedup 1.0000x reference)
#include <cuda_runtime.h>
#include <cuda_fp16.h>

#define BATCH 16
#define C_IN  64
#define C_OUT 32
#define V_HI  163842
#define V_LO  40962
#define KNB   7

#define TILES ((V_LO + 255) / 256)        // 161 tiles of 256 vertices
#define NEIGH_BLOCKS ((V_LO + 255) / 256) // 161

// Precomputed neigh table: g_neigh8[v*8+k] = up_neigh[down[v]*7 + k], stride 8.
__device__ int g_neigh8[V_LO * 8];

// Prolog: blocks [0,161) build the neighbor table; the rest zero d_out
// (atomicMax identity) with coalesced uint4 stores at streaming bandwidth.
__global__ __launch_bounds__(256) void prolog_kernel(
    const int* __restrict__ up_neigh,
    const int* __restrict__ down,
    unsigned int* __restrict__ out32,
    long long n4)
{
    if (blockIdx.x < NEIGH_BLOCKS) {
        int v = blockIdx.x * 256 + threadIdx.x;
        if (v >= V_LO) return;
        int dv = down[v];
        const int* src = up_neigh + (long long)dv * KNB;
#pragma unroll
        for (int k = 0; k < KNB; k++) g_neigh8[v * 8 + k] = src[k];
        g_neigh8[v * 8 + 7] = 0;
    } else {
        long long i = (long long)(blockIdx.x - NEIGH_BLOCKS) * 256 + threadIdx.x;
        if (i >= n4) return;
        reinterpret_cast<uint4*>(out32)[i] = make_uint4(0u, 0u, 0u, 0u);
    }
}

// Fused GEMV + packed-atomicMax scatter (R1-proven body, plain RED.MAX.U32).
// h[b,:,v] = W @ x[b,:,v] + bias; for each o:
//   u = neigh[v][mpi[b,o,v]];  atomicMax(out32[b,o,u], ((v+1)<<16) | fp16(h[o]))
// Winner = largest v (matches reference sequential-scatter last-write-wins;
// collisions only occur within one (b,o) slice).
__global__ __launch_bounds__(256) void fused_gemm_scatter_kernel(
    const float* __restrict__ x,
    const float* __restrict__ W,
    const float* __restrict__ bias,
    const int*   __restrict__ mpi,
    unsigned int* __restrict__ out32)
{
    __shared__ float sW[C_IN][C_OUT + 1];   // transposed, padded
    __shared__ float sB[C_OUT];

    int tid = threadIdx.x;
    for (int i = tid; i < C_IN * C_OUT; i += 256) {
        int o = i / C_IN;
        int c = i % C_IN;
        sW[c][o] = W[i];
    }
    if (tid < C_OUT) sB[tid] = bias[tid];
    __syncthreads();

    int v = blockIdx.x * 256 + tid;
    int b = blockIdx.y;
    if (v >= V_LO) return;

    // GEMV slice: h[o] = bias[o] + sum_c W[o][c] * x[b][c][v]
    float h[C_OUT];
#pragma unroll
    for (int o = 0; o < C_OUT; o++) h[o] = sB[o];

    const float* xp = x + ((long long)b * C_IN) * V_LO + v;
#pragma unroll
    for (int c = 0; c < C_IN; c++) {
        float xc = __ldg(xp + (long long)c * V_LO);
#pragma unroll
        for (int o = 0; o < C_OUT; o++) h[o] = fmaf(xc, sW[c][o], h[o]);
    }

    // Pack (v+1) in high 16 bits, fp16 value in low 16 bits.
    unsigned int vtag = ((unsigned int)(v + 1)) << 16;
    unsigned int ph[C_OUT];
#pragma unroll
    for (int o = 0; o < C_OUT; o++) {
        unsigned short hb = __half_as_ushort(__float2half_rn(h[o]));
        ph[o] = vtag | (unsigned int)hb;
    }

    // 7 neighbor ids for this v (contiguous 32B, coalesced across threads).
    const int4* np = reinterpret_cast<const int4*>(&g_neigh8[v * 8]);
    int4 n0 = np[0];
    int4 n1 = np[1];
    int nb[8] = {n0.x, n0.y, n0.z, n0.w, n1.x, n1.y, n1.z, n1.w};

    const int* mp = mpi + ((long long)b * C_OUT) * V_LO + v;
    unsigned int* ob = out32 + ((long long)b * C_OUT) * V_HI;

#pragma unroll
    for (int o = 0; o < C_OUT; o++) {
        int k = __ldg(mp + (long long)o * V_LO);   // coalesced
        int u = nb[k];
        atomicMax(&ob[(long long)o * V_HI + u], ph[o]);  // plain RED.MAX.U32
    }
}

// In-place decode: 0 -> 0.0f (already zero from prolog -> SKIP the write),
// else float(fp16 low half). Writes only uint4s containing a nonzero word.
__global__ __launch_bounds__(256) void finalize_kernel(unsigned int* __restrict__ buf,
                                                       long long n4)
{
    long long i = (long long)blockIdx.x * blockDim.x + threadIdx.x;
    if (i >= n4) return;
    uint4 p = reinterpret_cast<uint4*>(buf)[i];
    if ((p.x | p.y | p.z | p.w) == 0u) return;   // untouched group: stays zero
    float4 f;
    f.x = p.x ? __half2float(__ushort_as_half((unsigned short)(p.x & 0xFFFFu))) : 0.0f;
    f.y = p.y ? __half2float(__ushort_as_half((unsigned short)(p.y & 0xFFFFu))) : 0.0f;
    f.z = p.z ? __half2float(__ushort_as_half((unsigned short)(p.z & 0xFFFFu))) : 0.0f;
    f.w = p.w ? __half2float(__ushort_as_half((unsigned short)(p.w & 0xFFFFu))) : 0.0f;
    reinterpret_cast<float4*>(buf)[i] = f;
}

extern "C" void kernel_launch(void* const* d_in, const int* in_sizes, int n_in,
                              void* d_out, int out_size) {
    const float* x    = (const float*)d_in[0];   // (16, 64, 40962) f32
    const float* W    = (const float*)d_in[1];   // (32, 64) f32
    const float* bias = (const float*)d_in[2];   // (32,) f32
    const int*   mpi  = (const int*)d_in[3];     // (16, 32, 40962) i32
    const int*   up   = (const int*)d_in[4];     // (163842, 7) i32
    const int*   down = (const int*)d_in[5];     // (40962,) i32

    unsigned int* out32 = (unsigned int*)d_out;  // aliases the f32 output buffer

    long long n4 = (long long)out_size / 4;
    unsigned fin_grid = (unsigned)((n4 + 255) / 256);

    // 1) heterogeneous prolog: build neigh table + zero output, one launch
    prolog_kernel<<<NEIGH_BLOCKS + fin_grid, 256>>>(up, down, out32, n4);

    // 2) fused GEMV + packed atomicMax scatter (one full-width launch)
    dim3 grid(TILES, BATCH);
    fused_gemm_scatter_kernel<<<grid, 256>>>(x, W, bias, mpi, out32);

    // 3) in-place decode to float (zero-skipping writes)
    finalize_kernel<<<fin_grid, 256>>>(out32, n4);
}